// round 4
// baseline (speedup 1.0000x reference)
#include <cuda_runtime.h>
#include <cstdint>

// Problem constants
#define NROWS   200000
#define KTOT    1280          // 256 (x) + 1024 (h_cat)

// GEMM tiling: 2 CTAs/SM
#define BM      128
#define BN      96            // 32 u | 32 o | 32 inner columns
#define BK      32
#define NSTAGE  3
#define NT      (KTOT / BK)   // 40

#define LDA     136           // A smem [k][m] row stride (floats)
#define LDB     36            // B smem [n][k] row stride (floats)
#define A_BYTES (BK * LDA * 4)            // 17408
#define B_BYTES (BN * LDB * 4)            // 13824
#define STAGE_BYTES (A_BYTES + B_BYTES)   // 31232
#define SMEM_TOTAL  (NSTAGE * STAGE_BYTES) // 93696
#define LDC     100           // epilogue exchange stride (floats)

// Packed tf32 weights: row c' = b*96 + seg*32 + jj  <->  output col seg*256 + b*32 + jj
__device__ float g_Bp[(size_t)768 * KTOT];

__device__ __forceinline__ float to_tf32(float x) {
    uint32_t u;
    asm("cvt.rna.tf32.f32 %0, %1;" : "=r"(u) : "f"(x));
    return __uint_as_float(u);
}

__device__ __forceinline__ uint32_t smem_u32(const void* p) {
    uint32_t a;
    asm("{ .reg .u64 t; cvta.to.shared.u64 t, %1; cvt.u32.u64 %0, t; }" : "=r"(a) : "l"(p));
    return a;
}

__device__ __forceinline__ void cp_async16(uint32_t dst, const void* src) {
    asm volatile("cp.async.ca.shared.global [%0], [%1], 16;" :: "r"(dst), "l"(src) : "memory");
}
#define CP_COMMIT()  asm volatile("cp.async.commit_group;" ::: "memory")
#define CP_WAIT1()   asm volatile("cp.async.wait_group 1;" ::: "memory")

__device__ __forceinline__ void mma_tf32(float d[4], const uint32_t a[4], const uint32_t b[2]) {
    asm volatile(
        "mma.sync.aligned.m16n8k8.row.col.f32.tf32.tf32.f32 "
        "{%0,%1,%2,%3}, {%4,%5,%6,%7}, {%8,%9}, {%0,%1,%2,%3};"
        : "+f"(d[0]), "+f"(d[1]), "+f"(d[2]), "+f"(d[3])
        : "r"(a[0]), "r"(a[1]), "r"(a[2]), "r"(a[3]), "r"(b[0]), "r"(b[1]));
}

// ---------------------------------------------------------------------------
// Kernel 1: pack weights, tf32-rounded, block-friendly row order.
//   c' = b*96 + seg*32 + jj ; output col = seg*256 + (b*32 + jj)
//   seg 0: u = W_ruo row 256+col (k<256) | U_ruo row 256+col (k>=256)
//   seg 1: o = W_ruo row 512+col        | U_ruo row 512+col
//   seg 2: inner = 0 (k<256)            | U_u2 row col
// ---------------------------------------------------------------------------
__global__ void pack_b_kernel(const float* __restrict__ W_ruo,
                              const float* __restrict__ U_ruo,
                              const float* __restrict__ U_u2) {
    int idx = blockIdx.x * 256 + threadIdx.x;
    if (idx >= 768 * KTOT) return;
    int cp = idx / KTOT;
    int k  = idx % KTOT;
    int b   = cp / 96;
    int r   = cp % 96;
    int seg = r / 32;
    int jj  = r % 32;
    int col = b * 32 + jj;
    float v;
    if (seg < 2) {
        int wrow = 256 + seg * 256 + col;
        v = (k < 256) ? W_ruo[wrow * 256 + k] : U_ruo[wrow * 1024 + (k - 256)];
    } else {
        v = (k < 256) ? 0.0f : U_u2[col * 1024 + (k - 256)];
    }
    g_Bp[idx] = to_tf32(v);
}

// ---------------------------------------------------------------------------
// Kernel 2: fused gather + GEMM + GRU epilogue.
// grid = (8 col blocks of 32 output cols, 1563 row blocks), 256 threads.
// Warp grid 4x2, warp tile 32x48.
// ---------------------------------------------------------------------------
__global__ __launch_bounds__(256, 2)
void gemm_kernel(const float* __restrict__ x,
                 const float* __restrict__ h_prev,
                 const int*   __restrict__ child_idx,
                 const int*   __restrict__ child_mask,
                 const float* __restrict__ b_ruo,
                 float*       __restrict__ out) {
    extern __shared__ float smem[];
    const uint32_t sbase = smem_u32(smem);

    const int tid  = threadIdx.x;
    const int warp = tid >> 5;
    const int lane = tid & 31;
    const int wm   = warp >> 1;       // 0..3 -> 32 rows each
    const int wn   = warp & 1;        // 0..1 -> 48 cols each
    const int g    = lane >> 2;       // 0..7
    const int t4   = lane & 3;        // 0..3

    const int rowBase = blockIdx.y * BM;
    const int c0      = blockIdx.x * BN;   // g_Bp row base

    // --- A gather state: thread owns row (tid&127), k-half (tid>>7)*16 ---
    const int  aRow = tid & 127;
    const int  kh   = (tid >> 7) * 16;
    const int  nRow = rowBase + aRow;
    const bool rv   = (nRow < NROWS);
    const int  srcRow = rv ? nRow : 0;
    int  cidx[4];
    bool cok[4];
#pragma unroll
    for (int j = 0; j < 4; j++) {
        if (rv) {
            cidx[j] = child_idx[nRow * 4 + j];
            cok[j]  = (child_mask[nRow * 4 + j] != 0);
        } else { cidx[j] = 0; cok[j] = false; }
    }

    float acc[2][6][4];
#pragma unroll
    for (int mt = 0; mt < 2; mt++)
#pragma unroll
        for (int nt = 0; nt < 6; nt++)
#pragma unroll
            for (int i = 0; i < 4; i++) acc[mt][nt][i] = 0.0f;

    float4 av[4];
    const float4 z4 = make_float4(0.f, 0.f, 0.f, 0.f);

    // Issue this thread's 16-float A load for k-tile at k0 (gathered)
    auto loadA = [&](int k0) {
        const int k = k0 + kh;
        if (k < 256) {
            const float4* p = (const float4*)(x + (size_t)srcRow * 256 + k);
#pragma unroll
            for (int j = 0; j < 4; j++) av[j] = p[j];
        } else {
            const int seg = (k - 256) >> 8;
            const int kk  = (k - 256) & 255;
            if (cok[seg]) {
                const float4* p = (const float4*)(h_prev + (size_t)cidx[seg] * 256 + kk);
#pragma unroll
                for (int j = 0; j < 4; j++) av[j] = p[j];
            } else {
#pragma unroll
                for (int j = 0; j < 4; j++) av[j] = z4;
            }
        }
    };

    // Round + store A transposed into stage s: As[k][m]
    auto storeA = [&](int s) {
        float* As = smem + s * (STAGE_BYTES / 4);
#pragma unroll
        for (int j = 0; j < 4; j++) {
            float v[4] = { av[j].x, av[j].y, av[j].z, av[j].w };
#pragma unroll
            for (int c = 0; c < 4; c++)
                As[(kh + j * 4 + c) * LDA + aRow] = to_tf32(v[c]);
        }
    };

    // cp.async B tile into stage s (96 rows x 32 k) -> 768 float4, 3/thread
    auto loadB = [&](int s, int k0) {
        const uint32_t bb = sbase + s * STAGE_BYTES + A_BYTES;
#pragma unroll
        for (int j = 0; j < 3; j++) {
            const int c    = tid + 256 * j;
            const int rowb = c >> 3;
            const int ch   = c & 7;
            cp_async16(bb + rowb * (LDB * 4) + ch * 16,
                       g_Bp + (size_t)(c0 + rowb) * KTOT + k0 + ch * 4);
        }
    };

    auto compute = [&](int s) {
        const float* As = smem + s * (STAGE_BYTES / 4);
        const float* Bs = As + BK * LDA;
#pragma unroll
        for (int ks = 0; ks < 4; ks++) {
            const int k8 = ks * 8;
            uint32_t a[2][4], b[6][2];
#pragma unroll
            for (int mt = 0; mt < 2; mt++) {
                const int m = wm * 32 + mt * 16 + g;
                a[mt][0] = __float_as_uint(As[(k8 + t4) * LDA + m]);
                a[mt][1] = __float_as_uint(As[(k8 + t4) * LDA + m + 8]);
                a[mt][2] = __float_as_uint(As[(k8 + t4 + 4) * LDA + m]);
                a[mt][3] = __float_as_uint(As[(k8 + t4 + 4) * LDA + m + 8]);
            }
#pragma unroll
            for (int nt = 0; nt < 6; nt++) {
                const int n = wn * 48 + nt * 8 + g;
                b[nt][0] = __float_as_uint(Bs[n * LDB + k8 + t4]);
                b[nt][1] = __float_as_uint(Bs[n * LDB + k8 + t4 + 4]);
            }
#pragma unroll
            for (int mt = 0; mt < 2; mt++)
#pragma unroll
                for (int nt = 0; nt < 6; nt++)
                    mma_tf32(acc[mt][nt], a[mt], b[nt]);
        }
    };

    // --- Prologue: stages 0,1 ---
#pragma unroll
    for (int s = 0; s < NSTAGE - 1; s++) {
        loadA(s * BK);
        storeA(s);
        loadB(s, s * BK);
        CP_COMMIT();
    }

    // --- Main pipeline ---
    for (int t = 0; t < NT; t++) {
        CP_WAIT1();
        __syncthreads();
        const int  tl = t + NSTAGE - 1;
        const bool dl = (tl < NT);
        if (dl) loadA(tl * BK);            // issue LDGs early; consumed after compute
        compute(t % NSTAGE);
        if (dl) {
            storeA(tl % NSTAGE);
            loadB(tl % NSTAGE, tl * BK);
        }
        CP_COMMIT();                       // empty group when !dl keeps wait_group accounting
    }

    // --- Epilogue: exchange through smem, fuse GRU math, write out ---
    __syncthreads();
    float* Cs = smem;                      // 128 x LDC floats = 51.2 KB, fits
#pragma unroll
    for (int mt = 0; mt < 2; mt++) {
        const int r = wm * 32 + mt * 16 + g;
#pragma unroll
        for (int nt = 0; nt < 6; nt++) {
            const int c = wn * 48 + nt * 8 + 2 * t4;
            *(float2*)&Cs[r * LDC + c]       = make_float2(acc[mt][nt][0], acc[mt][nt][1]);
            *(float2*)&Cs[(r + 8) * LDC + c] = make_float2(acc[mt][nt][2], acc[mt][nt][3]);
        }
    }
    __syncthreads();

    const int bcol = blockIdx.x * 32;      // global output column base
#pragma unroll
    for (int it = 0; it < 4; it++) {
        const int lin = it * 256 + tid;    // 0..1023 over 128 rows x 8 quads
        const int row = lin >> 3;
        const int jj  = (lin & 7) * 4;
        const int n   = rowBase + row;
        float4 u4 = *(const float4*)&Cs[row * LDC + jj];
        float4 o4 = *(const float4*)&Cs[row * LDC + 32 + jj];
        float4 i4 = *(const float4*)&Cs[row * LDC + 64 + jj];
        float4 bu = *(const float4*)(b_ruo + 256 + bcol + jj);
        float4 bo = *(const float4*)(b_ruo + 512 + bcol + jj);
        float4 res;
#pragma unroll
        for (int c = 0; c < 4; c++) {
            float u = (&u4.x)[c] + (&bu.x)[c];
            float o = (&o4.x)[c] + (&bo.x)[c];
            float h = (&i4.x)[c];
            u = 1.0f / (1.0f + __expf(-u));
            o = tanhf(o);
            (&res.x)[c] = o * u + (1.0f - u) * h;
        }
        if (n < NROWS)
            *(float4*)(out + (size_t)n * 256 + bcol + jj) = res;
    }
}

// ---------------------------------------------------------------------------
extern "C" void kernel_launch(void* const* d_in, const int* in_sizes, int n_in,
                              void* d_out, int out_size) {
    const float* x          = (const float*)d_in[0];
    const float* h_prev     = (const float*)d_in[1];
    const float* W_ruo      = (const float*)d_in[2];
    const float* U_ruo      = (const float*)d_in[3];
    const float* b_ruo      = (const float*)d_in[4];
    const float* U_u2       = (const float*)d_in[5];
    const int*   child_idx  = (const int*)d_in[6];
    const int*   child_mask = (const int*)d_in[7];
    float*       out        = (float*)d_out;

    cudaFuncSetAttribute(gemm_kernel, cudaFuncAttributeMaxDynamicSharedMemorySize, SMEM_TOTAL);

    pack_b_kernel<<<(768 * KTOT + 255) / 256, 256>>>(W_ruo, U_ruo, U_u2);

    dim3 grid(8, (NROWS + BM - 1) / BM);   // (8, 1563)
    gemm_kernel<<<grid, 256, SMEM_TOTAL>>>(x, h_prev, child_idx, child_mask, b_ruo, out);
}

// round 5
// speedup vs baseline: 1.3006x; 1.3006x over previous
#include <cuda_runtime.h>
#include <cstdint>

// Problem constants
#define NROWS   200000
#define KTOT    1280          // 256 (x) + 1024 (h_cat)

// GEMM tiling: BM=128, BN=192 (64 u | 64 o | 64 inner), 2 CTAs/SM
#define BM      128
#define BN      192
#define BK      32
#define NT      (KTOT / BK)   // 40

#define LDKA    36            // A smem [m][k] row stride (floats): mod32=4 -> conflict-free
#define LDKB    40            // B smem [n][k] row stride (floats): mod32=8 -> LDS.64 conflict-free
#define A_BYTES (BM * LDKA * 4)            // 18432
#define B_BYTES (BN * LDKB * 4)            // 30720
#define STAGE_BYTES (A_BYTES + B_BYTES)    // 49152
#define SMEM_TOTAL  (2 * STAGE_BYTES)      // 98304 (2 CTAs -> 196608 < 228KB)
#define LDC     196           // epilogue exchange stride (floats)

// Packed tf32 weights, row cp = b*192 + seg*64 + jj <-> output col seg*256 + b*64 + jj.
// Within each 8-k block, k is permuted (i -> 2*(i&3) + (i>>2)) so B fragment
// pairs (t4, t4+4) sit adjacent -> LDS.64 fragment loads.
__device__ float g_Bp[(size_t)768 * KTOT];
__device__ __align__(16) float g_zero[16];   // zero-initialized

__device__ __forceinline__ float to_tf32(float x) {
    uint32_t u;
    asm("cvt.rna.tf32.f32 %0, %1;" : "=r"(u) : "f"(x));
    return __uint_as_float(u);
}

__device__ __forceinline__ uint32_t smem_u32(const void* p) {
    uint32_t a;
    asm("{ .reg .u64 t; cvta.to.shared.u64 t, %1; cvt.u32.u64 %0, t; }" : "=r"(a) : "l"(p));
    return a;
}

__device__ __forceinline__ void cp_async16(uint32_t dst, const void* src) {
    asm volatile("cp.async.ca.shared.global [%0], [%1], 16;" :: "r"(dst), "l"(src) : "memory");
}
#define CP_COMMIT()  asm volatile("cp.async.commit_group;" ::: "memory")
#define CP_WAIT0()   asm volatile("cp.async.wait_group 0;" ::: "memory")

__device__ __forceinline__ void mma_tf32(float d[4], const uint32_t a[4],
                                         uint32_t b0, uint32_t b1) {
    asm volatile(
        "mma.sync.aligned.m16n8k8.row.col.f32.tf32.tf32.f32 "
        "{%0,%1,%2,%3}, {%4,%5,%6,%7}, {%8,%9}, {%0,%1,%2,%3};"
        : "+f"(d[0]), "+f"(d[1]), "+f"(d[2]), "+f"(d[3])
        : "r"(a[0]), "r"(a[1]), "r"(a[2]), "r"(a[3]), "r"(b0), "r"(b1));
}

// ---------------------------------------------------------------------------
// Kernel 1: pack weights, tf32-rounded, block row order + k permutation.
// ---------------------------------------------------------------------------
__global__ void pack_b_kernel(const float* __restrict__ W_ruo,
                              const float* __restrict__ U_ruo,
                              const float* __restrict__ U_u2) {
    int idx = blockIdx.x * 256 + threadIdx.x;
    if (idx >= 768 * KTOT) return;
    int cp    = idx / KTOT;
    int k_out = idx % KTOT;
    // invert within-8 permutation: output slot o holds source i = (o>>1) + 4*(o&1)
    int o = k_out & 7;
    int k = (k_out & ~7) | ((o >> 1) + ((o & 1) << 2));
    int b   = cp / 192;
    int r   = cp % 192;
    int seg = r / 64;
    int jj  = r % 64;
    int col = b * 64 + jj;
    float v;
    if (seg < 2) {
        int wrow = 256 + seg * 256 + col;
        v = (k < 256) ? W_ruo[wrow * 256 + k] : U_ruo[wrow * 1024 + (k - 256)];
    } else {
        v = (k < 256) ? 0.0f : U_u2[col * 1024 + (k - 256)];
    }
    g_Bp[idx] = to_tf32(v);
}

// ---------------------------------------------------------------------------
// Kernel 2: fused gather + GEMM + GRU epilogue.
// grid = (4 col blocks of 64 output cols, 1563 row blocks), 256 threads.
// 8 warps in 2x4, warp tile 64x48. All operand staging via cp.async.
// ---------------------------------------------------------------------------
__global__ __launch_bounds__(256, 2)
void gemm_kernel(const float* __restrict__ x,
                 const float* __restrict__ h_prev,
                 const int*   __restrict__ child_idx,
                 const int*   __restrict__ child_mask,
                 const float* __restrict__ b_ruo,
                 float*       __restrict__ out) {
    extern __shared__ float smem[];
    const uint32_t sbase = smem_u32(smem);

    const int tid  = threadIdx.x;
    const int warp = tid >> 5;
    const int lane = tid & 31;
    const int wm   = warp >> 2;       // 0..1 -> 64 rows each
    const int wn   = warp & 3;        // 0..3 -> 48 cols each
    const int g    = lane >> 2;       // 0..7
    const int t4   = lane & 3;        // 0..3

    const int rowBase = blockIdx.y * BM;
    const int c0      = blockIdx.x * BN;   // g_Bp row base

    // --- A gather state: thread owns row tid>>1, k-half (tid&1)*16 ---
    const int  aRow = tid >> 1;
    const int  kh   = (tid & 1) * 16;
    const int  nRow = rowBase + aRow;
    const bool rv   = (nRow < NROWS);
    int cidx[4];                       // child row, or -1 if masked
#pragma unroll
    for (int j = 0; j < 4; j++) {
        if (rv) {
            int ci = child_idx[nRow * 4 + j];
            cidx[j] = (child_mask[nRow * 4 + j] != 0) ? ci : -1;
        } else cidx[j] = -1;
    }

    float acc[4][6][4];
#pragma unroll
    for (int mt = 0; mt < 4; mt++)
#pragma unroll
        for (int nt = 0; nt < 6; nt++)
#pragma unroll
            for (int i = 0; i < 4; i++) acc[mt][nt][i] = 0.0f;

    // cp.async A tile for k-tile t into stage s (this thread: 4 x 16B)
    auto loadA = [&](int t, int s) {
        const int k0 = t * BK;
        const uint32_t dst = sbase + s * STAGE_BYTES + aRow * (LDKA * 4) + kh * 4;
        const float* src;
        if (!rv) {
            src = g_zero;
        } else if (k0 < 256) {
            src = x + (size_t)nRow * 256 + k0 + kh;
        } else {
            const int seg = (k0 + kh - 256) >> 8;
            const int ci  = cidx[seg];
            src = (ci >= 0) ? h_prev + (size_t)ci * 256 + ((k0 - 256) & 255) + kh
                            : g_zero;
        }
        if (src == g_zero) {
#pragma unroll
            for (int j = 0; j < 4; j++) cp_async16(dst + j * 16, g_zero);
        } else {
#pragma unroll
            for (int j = 0; j < 4; j++) cp_async16(dst + j * 16, src + j * 4);
        }
    };

    // cp.async B tile (192 rows x 32 k -> 1536 chunks, 6/thread)
    auto loadB = [&](int t, int s) {
        const int k0 = t * BK;
        const uint32_t bb = sbase + s * STAGE_BYTES + A_BYTES;
#pragma unroll
        for (int j = 0; j < 6; j++) {
            const int c    = tid + 256 * j;
            const int rowb = c >> 3;
            const int ch   = c & 7;
            cp_async16(bb + rowb * (LDKB * 4) + ch * 16,
                       g_Bp + (size_t)(c0 + rowb) * KTOT + k0 + ch * 4);
        }
    };

    auto compute = [&](int s) {
        const float* As = smem + s * (STAGE_BYTES / 4);
        const float* Bs = As + A_BYTES / 4;
#pragma unroll
        for (int ks = 0; ks < 4; ks++) {
            uint2 bfr[6];
#pragma unroll
            for (int nt = 0; nt < 6; nt++)
                bfr[nt] = *(const uint2*)&Bs[(wn * 48 + nt * 8 + g) * LDKB + ks * 8 + 2 * t4];
#pragma unroll
            for (int mt = 0; mt < 4; mt++) {
                const float* ar = As + (wm * 64 + mt * 16 + g) * LDKA + ks * 8;
                uint32_t a[4];
                a[0] = __float_as_uint(ar[t4]);
                a[1] = __float_as_uint(ar[8 * LDKA + t4]);
                a[2] = __float_as_uint(ar[t4 + 4]);
                a[3] = __float_as_uint(ar[8 * LDKA + t4 + 4]);
#pragma unroll
                for (int nt = 0; nt < 6; nt++)
                    mma_tf32(acc[mt][nt], a, bfr[nt].x, bfr[nt].y);
            }
        }
    };

    // --- 2-stage pipeline ---
    loadA(0, 0); loadB(0, 0); CP_COMMIT();
    for (int t = 0; t < NT; t++) {
        CP_WAIT0();                     // this thread's tile t complete
        __syncthreads();                // all threads loaded t; all done compute(t-1)
        if (t + 1 < NT) {               // overlap t+1 loads with compute(t)
            loadA(t + 1, (t + 1) & 1);
            loadB(t + 1, (t + 1) & 1);
            CP_COMMIT();
        }
        compute(t & 1);
    }

    // --- Epilogue: two half-passes through smem, fused GRU math ---
    __syncthreads();
    float* Cs = smem;                   // 64 x LDC floats = 50176 B per pass
    const int bcol = blockIdx.x * 64;
#pragma unroll
    for (int p = 0; p < 2; p++) {
        if (wm == p) {
#pragma unroll
            for (int mt = 0; mt < 4; mt++) {
                const int r = mt * 16 + g;
#pragma unroll
                for (int nt = 0; nt < 6; nt++) {
                    const int c = wn * 48 + nt * 8 + 2 * t4;
                    *(float2*)&Cs[r * LDC + c]       = make_float2(acc[mt][nt][0], acc[mt][nt][1]);
                    *(float2*)&Cs[(r + 8) * LDC + c] = make_float2(acc[mt][nt][2], acc[mt][nt][3]);
                }
            }
        }
        __syncthreads();
#pragma unroll
        for (int it = 0; it < 4; it++) {
            const int lin = it * 256 + tid;   // 64 rows x 16 quads
            const int row = lin >> 4;
            const int jj  = (lin & 15) * 4;
            const int n   = rowBase + p * 64 + row;
            float4 u4 = *(const float4*)&Cs[row * LDC + jj];
            float4 o4 = *(const float4*)&Cs[row * LDC + 64 + jj];
            float4 i4 = *(const float4*)&Cs[row * LDC + 128 + jj];
            float4 bu = *(const float4*)(b_ruo + 256 + bcol + jj);
            float4 bo = *(const float4*)(b_ruo + 512 + bcol + jj);
            float4 res;
#pragma unroll
            for (int c = 0; c < 4; c++) {
                float u = (&u4.x)[c] + (&bu.x)[c];
                float o = (&o4.x)[c] + (&bo.x)[c];
                float h = (&i4.x)[c];
                u = 1.0f / (1.0f + __expf(-u));
                o = tanhf(o);
                (&res.x)[c] = o * u + (1.0f - u) * h;
            }
            if (n < NROWS)
                *(float4*)(out + (size_t)n * 256 + bcol + jj) = res;
        }
        __syncthreads();
    }
}

// ---------------------------------------------------------------------------
extern "C" void kernel_launch(void* const* d_in, const int* in_sizes, int n_in,
                              void* d_out, int out_size) {
    const float* x          = (const float*)d_in[0];
    const float* h_prev     = (const float*)d_in[1];
    const float* W_ruo      = (const float*)d_in[2];
    const float* U_ruo      = (const float*)d_in[3];
    const float* b_ruo      = (const float*)d_in[4];
    const float* U_u2       = (const float*)d_in[5];
    const int*   child_idx  = (const int*)d_in[6];
    const int*   child_mask = (const int*)d_in[7];
    float*       out        = (float*)d_out;

    cudaFuncSetAttribute(gemm_kernel, cudaFuncAttributeMaxDynamicSharedMemorySize, SMEM_TOTAL);

    pack_b_kernel<<<(768 * KTOT + 255) / 256, 256>>>(W_ruo, U_ruo, U_u2);

    dim3 grid(4, (NROWS + BM - 1) / BM);   // (4, 1563)
    gemm_kernel<<<grid, 256, SMEM_TOTAL>>>(x, h_prev, child_idx, child_mask, b_ruo, out);
}